// round 15
// baseline (speedup 1.0000x reference)
#include <cuda_runtime.h>
#include <cstdint>

// MaxUnpooling2D gather — FINAL kernel (converged; held through rounds 11-14).
//   B=16, H=W=128, C=64, UP=2 -> HO=WO=256.
//
// The reference's argmax indices always land inside their own 2x2 upsample
// window, so the scatter inverts to a gather with no atomics and no zero-fill:
//   out[b,ho,wo,c] = (mask[b,ho/2,wo/2,c] == (ho*WO+wo)*C + c)
//                    ? updates[b,ho/2,wo/2,c] : 0
//
// Roofline (validated over 7 structural variants + analytic elimination):
//   bytes: 268.4 MB output writes + 134.2 MB input reads = 402.6 MB irreducible
//   rate:  ~6.0 TB/s achieved (73-76% of spec; 2:1 write:read turnaround
//          ceiling — SM-side metrics all show headroom, limit is DRAM-side)
//   floor: 57.2-58.9 us kernel / 63.6-64.2 us e2e (7-run noise band of this
//          exact binary)  <- this kernel sits on it
// Falsified: extra MLP, .cs / L2-evict hints, 512-thr blocks, persistent
// single-wave grid (regressed). Analytically eliminated: store-contiguity
// remap (L2 decouples writeback from store order), TMA stores (LTS path-
// independent), mask compression (sector-granular reads + determinism rule).
//
// Thread = (b, h, w, c8), c8 in 0..7: 2 x LDG.256 + 4 x STG.256 per 2x2
// window. 2,097,152 threads = 8192 blocks x 256.

__device__ __forceinline__ void ldg_v8_f32(const float* p, float u[8]) {
    asm volatile("ld.global.v8.f32 {%0,%1,%2,%3,%4,%5,%6,%7}, [%8];"
                 : "=f"(u[0]), "=f"(u[1]), "=f"(u[2]), "=f"(u[3]),
                   "=f"(u[4]), "=f"(u[5]), "=f"(u[6]), "=f"(u[7])
                 : "l"(p));
}

__device__ __forceinline__ void ldg_v8_b32(const int* p, int m[8]) {
    asm volatile("ld.global.v8.b32 {%0,%1,%2,%3,%4,%5,%6,%7}, [%8];"
                 : "=r"(m[0]), "=r"(m[1]), "=r"(m[2]), "=r"(m[3]),
                   "=r"(m[4]), "=r"(m[5]), "=r"(m[6]), "=r"(m[7])
                 : "l"(p));
}

__device__ __forceinline__ void stg_v8_f32(float* p, const float s[8]) {
    asm volatile("st.global.v8.f32 [%0], {%1,%2,%3,%4,%5,%6,%7,%8};"
                 :: "l"(p),
                    "f"(s[0]), "f"(s[1]), "f"(s[2]), "f"(s[3]),
                    "f"(s[4]), "f"(s[5]), "f"(s[6]), "f"(s[7])
                 : "memory");
}

__device__ __forceinline__ void emit_pos(float* p, int tbase,
                                         const int m[8], const float u[8]) {
    float s[8];
#pragma unroll
    for (int i = 0; i < 8; i++)
        s[i] = (m[i] == tbase + i) ? u[i] : 0.0f;
    stg_v8_f32(p, s);
}

__global__ void __launch_bounds__(256)
unpool_v8_kernel(const float* __restrict__ upd,
                 const int*  __restrict__ mask,
                 float* __restrict__ out) {
    int g = blockIdx.x * blockDim.x + threadIdx.x;   // 0 .. 2^21-1

    int c8 = g & 7;             // which 8-float chunk of the 64 channels
    int w  = (g >> 3) & 127;
    int h  = (g >> 10) & 127;
    int b  = g >> 17;

    // input 8-elem chunk index (== g, same linearization)
    int in_chunk = ((((b << 7) + h) << 7) + w) * 8 + c8;

    int   m[8];
    float u[8];
    ldg_v8_b32(mask + in_chunk * 8, m);
    ldg_v8_f32(upd  + in_chunk * 8, u);

    int ho = h << 1;
    int wo = w << 1;

    // flat output ELEMENT index of this chunk's first channel at (ho, wo):
    int t00 = (((ho << 8) + wo) << 6) + (c8 << 3);
    int t10 = t00 + 16384;      // +WO*C for ho+1

    // output 8-elem chunk index of (b, ho, wo, c8):
    int o00 = ((((b << 8) + ho) << 8) + wo) * 8 + c8;
    // deltas (in chunks): +8 per wo step, +2048 per ho step

    emit_pos(out + (o00        ) * 8, t00,      m, u);   // (ho,   wo  )
    emit_pos(out + (o00 +    8 ) * 8, t00 + 64, m, u);   // (ho,   wo+1)
    emit_pos(out + (o00 + 2048 ) * 8, t10,      m, u);   // (ho+1, wo  )
    emit_pos(out + (o00 + 2056 ) * 8, t10 + 64, m, u);   // (ho+1, wo+1)
}

extern "C" void kernel_launch(void* const* d_in, const int* in_sizes, int n_in,
                              void* d_out, int out_size) {
    const float* upd  = (const float*)d_in[0];   // updates: [16,128,128,64] f32
    const int*   mask = (const int*)  d_in[1];   // mask:    [16,128,128,64] i32
    float*       out  = (float*)d_out;           // out:     [16,256,256,64] f32

    const int total_threads = 16 * 128 * 128 * 8; // 2,097,152
    const int threads = 256;
    const int blocks = total_threads / threads;   // 8192

    unpool_v8_kernel<<<blocks, threads>>>(upd, mask, out);
}

// round 16
// speedup vs baseline: 1.0111x; 1.0111x over previous
#include <cuda_runtime.h>
#include <cstdint>

// MaxUnpooling2D gather — FINAL kernel (converged; held rounds 11-15).
//   B=16, H=W=128, C=64, UP=2 -> HO=WO=256.
//
// The reference's argmax indices always land inside their own 2x2 upsample
// window, so the scatter inverts to a gather with no atomics and no zero-fill:
//   out[b,ho,wo,c] = (mask[b,ho/2,wo/2,c] == (ho*WO+wo)*C + c)
//                    ? updates[b,ho/2,wo/2,c] : 0
//
// Roofline (8 measurements of this binary; 7 structural variants tested):
//   bytes: 268.4 MB output writes + 134.2 MB input reads = 402.6 MB irreducible
//   rate:  ~6.0 TB/s achieved (73-76% of spec; 2:1 write:read turnaround
//          ceiling — SM-side metrics all show headroom, limit is DRAM-side)
//   band:  57.2-58.9 us kernel / 63.6-64.3 us e2e  <- this kernel sits on it
// Falsified: extra MLP, .cs / L2-evict hints, 512-thr blocks, persistent
// single-wave grid (regressed). Analytically eliminated: store-contiguity
// remap, TMA stores (LTS path-independent), mask compression, block-order
// swizzle (L2 at 42% — not the binding resource).
//
// Thread = (b, h, w, c8), c8 in 0..7: 2 x LDG.256 + 4 x STG.256 per 2x2
// window. 2,097,152 threads = 8192 blocks x 256.

__device__ __forceinline__ void ldg_v8_f32(const float* p, float u[8]) {
    asm volatile("ld.global.v8.f32 {%0,%1,%2,%3,%4,%5,%6,%7}, [%8];"
                 : "=f"(u[0]), "=f"(u[1]), "=f"(u[2]), "=f"(u[3]),
                   "=f"(u[4]), "=f"(u[5]), "=f"(u[6]), "=f"(u[7])
                 : "l"(p));
}

__device__ __forceinline__ void ldg_v8_b32(const int* p, int m[8]) {
    asm volatile("ld.global.v8.b32 {%0,%1,%2,%3,%4,%5,%6,%7}, [%8];"
                 : "=r"(m[0]), "=r"(m[1]), "=r"(m[2]), "=r"(m[3]),
                   "=r"(m[4]), "=r"(m[5]), "=r"(m[6]), "=r"(m[7])
                 : "l"(p));
}

__device__ __forceinline__ void stg_v8_f32(float* p, const float s[8]) {
    asm volatile("st.global.v8.f32 [%0], {%1,%2,%3,%4,%5,%6,%7,%8};"
                 :: "l"(p),
                    "f"(s[0]), "f"(s[1]), "f"(s[2]), "f"(s[3]),
                    "f"(s[4]), "f"(s[5]), "f"(s[6]), "f"(s[7])
                 : "memory");
}

__device__ __forceinline__ void emit_pos(float* p, int tbase,
                                         const int m[8], const float u[8]) {
    float s[8];
#pragma unroll
    for (int i = 0; i < 8; i++)
        s[i] = (m[i] == tbase + i) ? u[i] : 0.0f;
    stg_v8_f32(p, s);
}

__global__ void __launch_bounds__(256)
unpool_v8_kernel(const float* __restrict__ upd,
                 const int*  __restrict__ mask,
                 float* __restrict__ out) {
    int g = blockIdx.x * blockDim.x + threadIdx.x;   // 0 .. 2^21-1

    int c8 = g & 7;             // which 8-float chunk of the 64 channels
    int w  = (g >> 3) & 127;
    int h  = (g >> 10) & 127;
    int b  = g >> 17;

    // input 8-elem chunk index (== g, same linearization)
    int in_chunk = ((((b << 7) + h) << 7) + w) * 8 + c8;

    int   m[8];
    float u[8];
    ldg_v8_b32(mask + in_chunk * 8, m);
    ldg_v8_f32(upd  + in_chunk * 8, u);

    int ho = h << 1;
    int wo = w << 1;

    // flat output ELEMENT index of this chunk's first channel at (ho, wo):
    int t00 = (((ho << 8) + wo) << 6) + (c8 << 3);
    int t10 = t00 + 16384;      // +WO*C for ho+1

    // output 8-elem chunk index of (b, ho, wo, c8):
    int o00 = ((((b << 8) + ho) << 8) + wo) * 8 + c8;
    // deltas (in chunks): +8 per wo step, +2048 per ho step

    emit_pos(out + (o00        ) * 8, t00,      m, u);   // (ho,   wo  )
    emit_pos(out + (o00 +    8 ) * 8, t00 + 64, m, u);   // (ho,   wo+1)
    emit_pos(out + (o00 + 2048 ) * 8, t10,      m, u);   // (ho+1, wo  )
    emit_pos(out + (o00 + 2056 ) * 8, t10 + 64, m, u);   // (ho+1, wo+1)
}

extern "C" void kernel_launch(void* const* d_in, const int* in_sizes, int n_in,
                              void* d_out, int out_size) {
    const float* upd  = (const float*)d_in[0];   // updates: [16,128,128,64] f32
    const int*   mask = (const int*)  d_in[1];   // mask:    [16,128,128,64] i32
    float*       out  = (float*)d_out;           // out:     [16,256,256,64] f32

    const int total_threads = 16 * 128 * 128 * 8; // 2,097,152
    const int threads = 256;
    const int blocks = total_threads / threads;   // 8192

    unpool_v8_kernel<<<blocks, threads>>>(upd, mask, out);
}